// round 10
// baseline (speedup 1.0000x reference)
#include <cuda_runtime.h>
#include <cstdint>

// Problem constants (fixed shapes)
#define B   4
#define NB  2048
#define BS  32
#define D   256
#define NF  512
#define NC  1024
#define D4  (D/4)              // 64 float4 per row
#define TILE_F4 (BS * D4)      // 2048 float4 per (b,f) tile (32 KB)

// Grid partition: scalar | coarse | fine (1 tile per fine CTA)
#define SCALAR_BLOCKS  64
#define COARSE_BLOCKS  256
#define FINE_CTAS      (B * NF)                       // 2048
#define TOTAL_BLOCKS   (SCALAR_BLOCKS + COARSE_BLOCKS + FINE_CTAS)

#define SMEM_BYTES (TILE_F4 * 16)                     // 32 KB staging buffer

__device__ __forceinline__ uint64_t make_evict_last_policy() {
    uint64_t p;
    asm("createpolicy.fractional.L2::evict_last.b64 %0, 1.0;" : "=l"(p));
    return p;
}
__device__ __forceinline__ uint64_t make_evict_first_policy() {
    uint64_t p;
    asm("createpolicy.fractional.L2::evict_first.b64 %0, 1.0;" : "=l"(p));
    return p;
}
__device__ __forceinline__ float4 ldg_evict_last(const float4* p, uint64_t pol) {
    float4 v;
    asm volatile("ld.global.nc.L2::cache_hint.v4.f32 {%0,%1,%2,%3}, [%4], %5;"
                 : "=f"(v.x), "=f"(v.y), "=f"(v.z), "=f"(v.w)
                 : "l"(p), "l"(pol));
    return v;
}

__global__ void __launch_bounds__(256) fused_kernel(
    const float4* __restrict__ coarse,    // [B,NB,D4]
    const float4* __restrict__ bank,      // [B,NB,BS,D4]
    const int*    __restrict__ fidx,      // [B,NF]
    const int*    __restrict__ table,     // [B,NB]
    const float*  __restrict__ ftm,       // [B, NB*BS]
    const float*  __restrict__ fscore,    // [B, NF]
    const float*  __restrict__ ctm,       // [B, NB]
    const int*    __restrict__ cidx,      // [B, NC]
    const float*  __restrict__ cscore,    // [B, NC]
    float4* __restrict__ o_fine_states,   // [B*NF] tiles of 2048 f4
    float*  __restrict__ o_fine_mask,
    float*  __restrict__ o_fine_scores,
    float*  __restrict__ o_fine_dups,
    float4* __restrict__ o_coarse_states, // [B,NC,D4]
    float*  __restrict__ o_coarse_mask,
    float*  __restrict__ o_coarse_scores,
    float*  __restrict__ o_coarse_dups)
{
    extern __shared__ __align__(128) float4 sbuf[];   // [TILE_F4] (fine path only)

    const unsigned bid = blockIdx.x;
    const unsigned t   = threadIdx.x;

    if (bid < SCALAR_BLOCKS) {
        // ---- all scalar outputs: 4 elements per thread ----
        #pragma unroll
        for (int j = 0; j < 4; j++) {
            const unsigned i = bid * 1024 + (unsigned)j * 256 + t;  // < 65536
            const unsigned s = i & (BS - 1);
            const unsigned f = (i >> 5) & (NF - 1);
            const unsigned b = i >> 14;

            const int fi = __ldg(&fidx[b * NF + f]);
            o_fine_mask[i]   = __ldg(&ftm[b * (NB * BS) + (unsigned)fi * BS + s]);
            o_fine_scores[i] = __ldg(&fscore[b * NF + f]);
            o_fine_dups[i]   = 1.0f;

            if (i < (unsigned)(B * NC)) {
                const unsigned c  = i & (NC - 1);
                const unsigned b2 = i >> 10;
                const int ci = __ldg(&cidx[b2 * NC + c]);
                o_coarse_mask[i]   = __ldg(&ctm[b2 * NB + (unsigned)ci]);
                o_coarse_scores[i] = __ldg(&cscore[i]);
                o_coarse_dups[i]   = 32.0f;
            }
        }
    }
    else if (bid < SCALAR_BLOCKS + COARSE_BLOCKS) {
        // ---- coarse token states gather: 4 float4 per thread ----
        const unsigned base = (bid - SCALAR_BLOCKS) * 1024;
        float4 v[4];
        #pragma unroll
        for (int j = 0; j < 4; j++) {
            const unsigned i  = base + (unsigned)j * 256 + t;  // < 2^18
            const unsigned d4 = i & (D4 - 1);
            const unsigned c  = (i >> 6) & (NC - 1);
            const unsigned b  = i >> 16;
            const int ci = __ldg(&cidx[b * NC + c]);
            v[j] = __ldg(&coarse[(b * NB + (unsigned)ci) * D4 + d4]);
        }
        #pragma unroll
        for (int j = 0; j < 4; j++)
            __stcs(&o_coarse_states[base + (unsigned)j * 256 + t], v[j]);
    }
    else {
        // ---- fine token states: one 32 KB tile per CTA, single bulk store ----
        const unsigned tile = bid - (SCALAR_BLOCKS + COARSE_BLOCKS);  // < 2048
        const unsigned b = tile >> 9;        // / NF
        const unsigned f = tile & (NF - 1);

        const int fi = __ldg(&fidx[b * NF + f]);
        // d4 of every element this thread touches is (t & 63): 256 % 64 == 0
        const float4 c = __ldg(&coarse[(b * NB + (unsigned)fi) * D4 + (t & (D4 - 1))]);
        const int bi = __ldg(&table[b * NB + fi]);

        const float4* __restrict__ bt = bank + (size_t)(b * NB + (unsigned)bi) * TILE_F4;

        const uint64_t lpol = make_evict_last_policy();

        // 8 independent evict-last loads (MLP=8)
        float4 v[8];
        #pragma unroll
        for (int j = 0; j < 8; j++)
            v[j] = ldg_evict_last(&bt[j * 256 + t], lpol);

        // compute into smem staging buffer
        #pragma unroll
        for (int j = 0; j < 8; j++)
            sbuf[j * 256 + t] = make_float4(c.x - v[j].x, c.y - v[j].y,
                                            c.z - v[j].z, c.w - v[j].w);

        // make generic-proxy smem writes visible to the async proxy
        asm volatile("fence.proxy.async.shared::cta;" ::: "memory");
        __syncthreads();

        if (t == 0) {
            const uint64_t spol = make_evict_first_policy();
            const uint32_t saddr = (uint32_t)__cvta_generic_to_shared(sbuf);
            float4* gdst = o_fine_states + (size_t)tile * TILE_F4;
            asm volatile(
                "cp.async.bulk.global.shared::cta.bulk_group.L2::cache_hint"
                " [%0], [%1], %2, %3;"
                :: "l"(gdst), "r"(saddr), "r"((uint32_t)SMEM_BYTES), "l"(spol)
                : "memory");
            asm volatile("cp.async.bulk.commit_group;" ::: "memory");
            // wait only for smem READ completion; DRAM drain overlaps next CTA
            asm volatile("cp.async.bulk.wait_group.read 0;" ::: "memory");
        }
        __syncthreads();
    }
}

extern "C" void kernel_launch(void* const* d_in, const int* in_sizes, int n_in,
                              void* d_out, int out_size)
{
    const float* fine_token_mask      = (const float*)d_in[0];
    const float* coarse_token_states  = (const float*)d_in[1];
    const float* coarse_token_mask    = (const float*)d_in[2];
    const int*   fine_block_indices   = (const int*)  d_in[3];
    const float* fine_block_scores    = (const float*)d_in[4];
    const int*   coarse_block_indices = (const int*)  d_in[5];
    const float* coarse_block_scores  = (const float*)d_in[6];
    const int*   cache_indice_table   = (const int*)  d_in[7];
    const float* cache_bank           = (const float*)d_in[8];

    float* out = (float*)d_out;

    const long long n_fine_states   = (long long)B * NF * BS * D;   // 16,777,216
    const long long n_fine_scalar   = (long long)B * NF * BS;       // 65,536
    const long long n_coarse_states = (long long)B * NC * D;        // 1,048,576
    const long long n_coarse_scalar = (long long)B * NC;            // 4,096

    float* o_fine_states   = out;
    float* o_fine_mask     = o_fine_states   + n_fine_states;
    float* o_fine_scores   = o_fine_mask     + n_fine_scalar;
    float* o_fine_dups     = o_fine_scores   + n_fine_scalar;
    float* o_coarse_states = o_fine_dups     + n_fine_scalar;
    float* o_coarse_mask   = o_coarse_states + n_coarse_states;
    float* o_coarse_scores = o_coarse_mask   + n_coarse_scalar;
    float* o_coarse_dups   = o_coarse_scores + n_coarse_scalar;

    cudaFuncSetAttribute(fused_kernel,
                         cudaFuncAttributeMaxDynamicSharedMemorySize,
                         (int)SMEM_BYTES);

    fused_kernel<<<TOTAL_BLOCKS, 256, SMEM_BYTES>>>(
        (const float4*)coarse_token_states,
        (const float4*)cache_bank,
        fine_block_indices,
        cache_indice_table,
        fine_token_mask,
        fine_block_scores,
        coarse_token_mask,
        coarse_block_indices,
        coarse_block_scores,
        (float4*)o_fine_states,
        o_fine_mask, o_fine_scores, o_fine_dups,
        (float4*)o_coarse_states,
        o_coarse_mask, o_coarse_scores, o_coarse_dups);
}

// round 11
// speedup vs baseline: 1.2980x; 1.2980x over previous
#include <cuda_runtime.h>
#include <cstdint>

// Problem constants (fixed shapes)
#define B   4
#define NB  2048
#define BS  32
#define D   256
#define NF  512
#define NC  1024
#define D4  (D/4)              // 64 float4 per row
#define TILE_F4 (BS * D4)      // 2048 float4 per (b,f) tile

// Grid partition: scalar | coarse | fine (1 tile per fine CTA)
#define SCALAR_BLOCKS  64      // 65536 scalars, 4 per thread
#define COARSE_BLOCKS  256     // 2^18 float4, 4 per thread
#define FINE_CTAS      (B * NF)                       // 2048
#define TOTAL_BLOCKS   (SCALAR_BLOCKS + COARSE_BLOCKS + FINE_CTAS)

// L2 evict-last access policy (pin the re-used bank read set in L2)
__device__ __forceinline__ uint64_t make_evict_last_policy() {
    uint64_t p;
    asm("createpolicy.fractional.L2::evict_last.b64 %0, 1.0;" : "=l"(p));
    return p;
}

__device__ __forceinline__ float4 ldg_evict_last(const float4* p, uint64_t pol) {
    float4 v;
    asm volatile("ld.global.nc.L2::cache_hint.v4.f32 {%0,%1,%2,%3}, [%4], %5;"
                 : "=f"(v.x), "=f"(v.y), "=f"(v.z), "=f"(v.w)
                 : "l"(p), "l"(pol));
    return v;
}

__global__ void __launch_bounds__(256) fused_kernel(
    const float4* __restrict__ coarse,    // [B,NB,D4]
    const float4* __restrict__ bank,      // [B,NB,BS,D4]
    const int*    __restrict__ fidx,      // [B,NF]
    const int*    __restrict__ table,     // [B,NB]
    const float*  __restrict__ ftm,       // [B, NB*BS]
    const float*  __restrict__ fscore,    // [B, NF]
    const float*  __restrict__ ctm,       // [B, NB]
    const int*    __restrict__ cidx,      // [B, NC]
    const float*  __restrict__ cscore,    // [B, NC]
    float4* __restrict__ o_fine_states,   // [B*NF] tiles of 2048 f4
    float*  __restrict__ o_fine_mask,
    float*  __restrict__ o_fine_scores,
    float*  __restrict__ o_fine_dups,
    float4* __restrict__ o_coarse_states, // [B,NC,D4]
    float*  __restrict__ o_coarse_mask,
    float*  __restrict__ o_coarse_scores,
    float*  __restrict__ o_coarse_dups)
{
    const unsigned bid = blockIdx.x;
    const unsigned t   = threadIdx.x;

    if (bid < SCALAR_BLOCKS) {
        // ---- all scalar outputs: 4 elements per thread ----
        #pragma unroll
        for (int j = 0; j < 4; j++) {
            const unsigned i = bid * 1024 + (unsigned)j * 256 + t;  // < 65536
            const unsigned s = i & (BS - 1);
            const unsigned f = (i >> 5) & (NF - 1);
            const unsigned b = i >> 14;

            const int fi = __ldg(&fidx[b * NF + f]);
            o_fine_mask[i]   = __ldg(&ftm[b * (NB * BS) + (unsigned)fi * BS + s]);
            o_fine_scores[i] = __ldg(&fscore[b * NF + f]);
            o_fine_dups[i]   = 1.0f;

            if (i < (unsigned)(B * NC)) {
                const unsigned c  = i & (NC - 1);
                const unsigned b2 = i >> 10;
                const int ci = __ldg(&cidx[b2 * NC + c]);
                o_coarse_mask[i]   = __ldg(&ctm[b2 * NB + (unsigned)ci]);
                o_coarse_scores[i] = __ldg(&cscore[i]);
                o_coarse_dups[i]   = 32.0f;
            }
        }
    }
    else if (bid < SCALAR_BLOCKS + COARSE_BLOCKS) {
        // ---- coarse token states gather: 4 float4 per thread (MLP=4) ----
        const unsigned base = (bid - SCALAR_BLOCKS) * 1024;
        float4 v[4];
        #pragma unroll
        for (int j = 0; j < 4; j++) {
            const unsigned i  = base + (unsigned)j * 256 + t;  // < 2^18
            const unsigned d4 = i & (D4 - 1);
            const unsigned c  = (i >> 6) & (NC - 1);
            const unsigned b  = i >> 16;
            const int ci = __ldg(&cidx[b * NC + c]);
            v[j] = __ldg(&coarse[(b * NB + (unsigned)ci) * D4 + d4]);
        }
        #pragma unroll
        for (int j = 0; j < 4; j++)
            __stcs(&o_coarse_states[base + (unsigned)j * 256 + t], v[j]);
    }
    else {
        // ---- fine token states: one tile per CTA, warp-contiguous 4KB chunks ----
        const unsigned tile = bid - (SCALAR_BLOCKS + COARSE_BLOCKS);  // < 2048
        const unsigned b = tile >> 9;        // / NF
        const unsigned f = tile & (NF - 1);

        const unsigned warp = t >> 5;        // 0..7: each warp owns contiguous 4KB
        const unsigned lane = t & 31u;
        const unsigned wbase = warp * 256;   // float4 offset of this warp's chunk

        const int fi = __ldg(&fidx[b * NF + f]);
        const int bi = __ldg(&table[b * NB + fi]);

        const float4* __restrict__ crow = &coarse[(b * NB + (unsigned)fi) * D4];
        const float4* __restrict__ bt = bank + (size_t)(b * NB + (unsigned)bi) * TILE_F4;
        float4*       __restrict__ ot = o_fine_states + (size_t)tile * TILE_F4;

        const uint64_t pol = make_evict_last_policy();

        // 8 independent evict-last loads per thread; warp stream is sequential
        // 512B chunks covering one contiguous 4KB region (same DRAM page).
        float4 v[8];
        #pragma unroll
        for (int j = 0; j < 8; j++)
            v[j] = ldg_evict_last(&bt[wbase + (unsigned)j * 32 + lane], pol);

        #pragma unroll
        for (int j = 0; j < 8; j++) {
            const unsigned idx = wbase + (unsigned)j * 32 + lane;
            const float4 c = __ldg(&crow[idx & (D4 - 1)]);
            __stcs(&ot[idx],
                   make_float4(c.x - v[j].x, c.y - v[j].y,
                               c.z - v[j].z, c.w - v[j].w));
        }
    }
}

extern "C" void kernel_launch(void* const* d_in, const int* in_sizes, int n_in,
                              void* d_out, int out_size)
{
    const float* fine_token_mask      = (const float*)d_in[0];
    const float* coarse_token_states  = (const float*)d_in[1];
    const float* coarse_token_mask    = (const float*)d_in[2];
    const int*   fine_block_indices   = (const int*)  d_in[3];
    const float* fine_block_scores    = (const float*)d_in[4];
    const int*   coarse_block_indices = (const int*)  d_in[5];
    const float* coarse_block_scores  = (const float*)d_in[6];
    const int*   cache_indice_table   = (const int*)  d_in[7];
    const float* cache_bank           = (const float*)d_in[8];

    float* out = (float*)d_out;

    const long long n_fine_states   = (long long)B * NF * BS * D;   // 16,777,216
    const long long n_fine_scalar   = (long long)B * NF * BS;       // 65,536
    const long long n_coarse_states = (long long)B * NC * D;        // 1,048,576
    const long long n_coarse_scalar = (long long)B * NC;            // 4,096

    float* o_fine_states   = out;
    float* o_fine_mask     = o_fine_states   + n_fine_states;
    float* o_fine_scores   = o_fine_mask     + n_fine_scalar;
    float* o_fine_dups     = o_fine_scores   + n_fine_scalar;
    float* o_coarse_states = o_fine_dups     + n_fine_scalar;
    float* o_coarse_mask   = o_coarse_states + n_coarse_states;
    float* o_coarse_scores = o_coarse_mask   + n_coarse_scalar;
    float* o_coarse_dups   = o_coarse_scores + n_coarse_scalar;

    fused_kernel<<<TOTAL_BLOCKS, 256>>>(
        (const float4*)coarse_token_states,
        (const float4*)cache_bank,
        fine_block_indices,
        cache_indice_table,
        fine_token_mask,
        fine_block_scores,
        coarse_token_mask,
        coarse_block_indices,
        coarse_block_scores,
        (float4*)o_fine_states,
        o_fine_mask, o_fine_scores, o_fine_dups,
        (float4*)o_coarse_states,
        o_coarse_mask, o_coarse_scores, o_coarse_dups);
}